// round 3
// baseline (speedup 1.0000x reference)
#include <cuda_runtime.h>
#include <stdint.h>

#define Bq   4
#define Cq   16
#define Hq   512
#define Wq   512
#define HWq  (Hq * Wq)          // 262144
#define NODES (Bq * HWq)        // 1048576
#define NF_ELEMS (NODES * Cq)   // 16777216
#define SQ2f 1.41421356237f

// Kernel A: (B,C,H,W) -> (B*H*W, C) transpose into first output region.
__global__ void __launch_bounds__(256) transpose_bchw_to_nc(
    const float* __restrict__ grid, float* __restrict__ out)
{
    int node = blockIdx.x * blockDim.x + threadIdx.x;
    if (node >= NODES) return;
    int b  = node >> 18;
    int hw = node & (HWq - 1);
    const float* g = grid + (size_t)b * Cq * HWq + hw;

    float v[Cq];
#pragma unroll
    for (int c = 0; c < Cq; c++) v[c] = g[(size_t)c * HWq];

    float4* dst = (float4*)(out + (size_t)node * Cq);
#pragma unroll
    for (int i = 0; i < 4; i++)
        dst[i] = make_float4(v[4*i], v[4*i+1], v[4*i+2], v[4*i+3]);
}

// Kernel B: node-centric 8-neighbor stencil, one block per row h,
// one thread per column w (512 threads). Scalar loads are fully coalesced
// per warp; horizontal neighbors via warp shuffle (+2 boundary loads).
__global__ void __launch_bounds__(512) attr_kernel(
    const float* __restrict__ grid,
    float* __restrict__ ei_out, float* __restrict__ attr, int E)
{
    const int h    = blockIdx.x;
    const int w    = threadIdx.x;
    const int lane = w & 31;

    const int hu = (h > 0)      ? h - 1 : 0;
    const int hd = (h < Hq - 1) ? h + 1 : Hq - 1;

    const float* pc = grid + (size_t)h  * Wq + w;
    const float* pu = grid + (size_t)hu * Wq + w;
    const float* pd = grid + (size_t)hd * Wq + w;

    const int lL = (w > 0)      ? -1 : 0;  // clamped halo offsets
    const int rR = (w < Wq - 1) ?  1 : 0;

    float acc[8];
#pragma unroll
    for (int k = 0; k < 8; k++) acc[k] = 0.0f;

#pragma unroll 4
    for (int bc = 0; bc < Bq * Cq; bc++) {
        float u = *pu, c = *pc, d = *pd;

        float uL = __shfl_up_sync(0xffffffffu, u, 1);
        float cL = __shfl_up_sync(0xffffffffu, c, 1);
        float dL = __shfl_up_sync(0xffffffffu, d, 1);
        float uR = __shfl_down_sync(0xffffffffu, u, 1);
        float cR = __shfl_down_sync(0xffffffffu, c, 1);
        float dR = __shfl_down_sync(0xffffffffu, d, 1);
        if (lane == 0)  { uL = pu[lL]; cL = pc[lL]; dL = pd[lL]; }
        if (lane == 31) { uR = pu[rR]; cR = pc[rR]; dR = pd[rR]; }

        acc[0] += fabsf(c - uL);
        acc[1] += fabsf(c - u);
        acc[2] += fabsf(c - uR);
        acc[3] += fabsf(c - cL);
        acc[4] += fabsf(c - cR);
        acc[5] += fabsf(c - dL);
        acc[6] += fabsf(c - d);
        acc[7] += fabsf(c - dR);

        pu += HWq; pc += HWq; pd += HWq;
    }

    // ---- analytic edge positions ----
    // edges per row: boundary rows 3+3+5*510 = 2556, interior 5+5+8*510 = 4090
    const int rowbase = (h == 0) ? 0 : (2556 + 4090 * (h - 1));
    const bool edgeRow = (h == 0) || (h == Hq - 1);
    const bool up_ok = (h > 0), dn_ok = (h < Hq - 1);
    const bool l_ok = (w > 0),  r_ok  = (w < Wq - 1);

    const int within = (w == 0) ? 0 : (edgeRow ? (3 + 5 * (w - 1))
                                               : (5 + 8 * (w - 1)));
    const int P = rowbase + within;
    const int n = h * Wq + w;

    const float dist[8] = {SQ2f, 1.0f, SQ2f, 1.0f, 1.0f, SQ2f, 1.0f, SQ2f};
    const int   doff[8] = {-Wq - 1, -Wq, -Wq + 1, -1, 1, Wq - 1, Wq, Wq + 1};
    const bool  v[8]    = { up_ok && l_ok, up_ok, up_ok && r_ok,
                            l_ok, r_ok,
                            dn_ok && l_ok, dn_ok, dn_ok && r_ok };
    const float inv = 1.0f / (float)(Bq * Cq);

    int slot = 0;
#pragma unroll
    for (int k = 0; k < 8; k++) {
        if (v[k]) {
            int e = P + slot;
            ((float2*)attr)[e] = make_float2(dist[k], acc[k] * inv);
            ei_out[e]     = (float)n;
            ei_out[E + e] = (float)(n + doff[k]);
            slot++;
        }
    }
}

extern "C" void kernel_launch(void* const* d_in, const int* in_sizes, int n_in,
                              void* d_out, int out_size)
{
    const float* grid = (const float*)d_in[0];
    const int E = in_sizes[1] / 2;

    float* out    = (float*)d_out;
    float* nf     = out;                    // [NODES, C]
    float* ei_out = out + NF_ELEMS;         // [2, E] as float
    float* attr   = ei_out + 2 * (size_t)E; // [E, 2]

    transpose_bchw_to_nc<<<(NODES + 255) / 256, 256>>>(grid, nf);
    attr_kernel<<<Hq, 512>>>(grid, ei_out, attr, E);
}

// round 6
// speedup vs baseline: 2.4077x; 2.4077x over previous
#include <cuda_runtime.h>
#include <stdint.h>

#define Bq   4
#define Cq   16
#define Hq   512
#define Wq   512
#define HWq  (Hq * Wq)          // 262144
#define NODES (Bq * HWq)        // 1048576
#define NF_ELEMS (NODES * Cq)   // 16777216
#define SQ2f 1.41421356237f
#define ATTR_BLOCKS 512         // one per image row
#define TRANS_BLOCKS (NODES / 256)

// Single fused kernel. Blocks [0, 512): node-centric stencil producing
// edge_attr + float edge_index (one row per block, 2 cols per thread, halo
// loaded directly from global — no shuffles, no barriers). Blocks [512, 4608):
// BCHW -> (B*H*W, C) transpose. Attr blocks are scheduled first so they stay
// resident while transpose blocks stream memory around them.
__global__ void __launch_bounds__(256) fused_kernel(
    const float* __restrict__ grid, float* __restrict__ nf,
    float* __restrict__ ei_out, float* __restrict__ attr, int E)
{
    if (blockIdx.x >= ATTR_BLOCKS) {
        // ---------------- transpose part ----------------
        int node = (blockIdx.x - ATTR_BLOCKS) * 256 + threadIdx.x;
        int b  = node >> 18;
        int hw = node & (HWq - 1);
        const float* g = grid + (size_t)b * Cq * HWq + hw;

        float v[Cq];
#pragma unroll
        for (int c = 0; c < Cq; c++) v[c] = g[(size_t)c * HWq];

        float4* dst = (float4*)(nf + (size_t)node * Cq);
#pragma unroll
        for (int i = 0; i < 4; i++)
            dst[i] = make_float4(v[4*i], v[4*i+1], v[4*i+2], v[4*i+3]);
        return;
    }

    // ---------------- attr part ----------------
    const int h  = blockIdx.x;
    const int w0 = threadIdx.x * 2;
    const int w1 = w0 + 1;

    const int hu = (h > 0)      ? h - 1 : 0;
    const int hd = (h < Hq - 1) ? h + 1 : Hq - 1;

    const float* pc = grid + (size_t)h  * Wq;
    const float* pu = grid + (size_t)hu * Wq;
    const float* pd = grid + (size_t)hd * Wq;

    const int wm = (w0 > 0)      ? w0 - 1 : 0;   // clamped halo cols
    const int wp = (w1 < Wq - 1) ? w1 + 1 : Wq - 1;

    float a0[8], a1[8];
#pragma unroll
    for (int k = 0; k < 8; k++) { a0[k] = 0.0f; a1[k] = 0.0f; }

#pragma unroll 4
    for (int bc = 0; bc < Bq * Cq; bc++) {
        float2 cu = *(const float2*)(pc + w0);
        float2 uu = *(const float2*)(pu + w0);
        float2 dd = *(const float2*)(pd + w0);
        float cl = pc[wm], cr = pc[wp];
        float ul = pu[wm], ur = pu[wp];
        float dl = pd[wm], dr = pd[wp];

        a0[0] += fabsf(cu.x - ul);
        a0[1] += fabsf(cu.x - uu.x);
        a0[2] += fabsf(cu.x - uu.y);
        a0[3] += fabsf(cu.x - cl);
        a0[4] += fabsf(cu.x - cu.y);
        a0[5] += fabsf(cu.x - dl);
        a0[6] += fabsf(cu.x - dd.x);
        a0[7] += fabsf(cu.x - dd.y);

        a1[0] += fabsf(cu.y - uu.x);
        a1[1] += fabsf(cu.y - uu.y);
        a1[2] += fabsf(cu.y - ur);
        a1[3] += fabsf(cu.y - cu.x);
        a1[4] += fabsf(cu.y - cr);
        a1[5] += fabsf(cu.y - dd.x);
        a1[6] += fabsf(cu.y - dd.y);
        a1[7] += fabsf(cu.y - dr);

        pu += HWq; pc += HWq; pd += HWq;
    }

    // ---- analytic edge positions ----
    // edges per row: boundary rows 3+3+5*510 = 2556, interior 5+5+8*510 = 4090
    const int rowbase = (h == 0) ? 0 : (2556 + 4090 * (h - 1));
    const bool edgeRow = (h == 0) || (h == Hq - 1);
    const bool up_ok = (h > 0), dn_ok = (h < Hq - 1);

    const float dist[8] = {SQ2f, 1.0f, SQ2f, 1.0f, 1.0f, SQ2f, 1.0f, SQ2f};
    const int   doff[8] = {-Wq - 1, -Wq, -Wq + 1, -1, 1, Wq - 1, Wq, Wq + 1};
    const float inv = 1.0f / (float)(Bq * Cq);

#pragma unroll
    for (int j = 0; j < 2; j++) {
        const int w = w0 + j;
        const float* acc = (j == 0) ? a0 : a1;
        const bool l_ok = (w > 0), r_ok = (w < Wq - 1);

        const int within = (w == 0) ? 0 : (edgeRow ? (3 + 5 * (w - 1))
                                                   : (5 + 8 * (w - 1)));
        const int P = rowbase + within;
        const int n = h * Wq + w;

        const bool v[8] = { up_ok && l_ok, up_ok, up_ok && r_ok,
                            l_ok, r_ok,
                            dn_ok && l_ok, dn_ok, dn_ok && r_ok };

        int slot = 0;
#pragma unroll
        for (int k = 0; k < 8; k++) {
            if (v[k]) {
                int e = P + slot;
                ((float2*)attr)[e] = make_float2(dist[k], acc[k] * inv);
                ei_out[e]     = (float)n;
                ei_out[E + e] = (float)(n + doff[k]);
                slot++;
            }
        }
    }
}

extern "C" void kernel_launch(void* const* d_in, const int* in_sizes, int n_in,
                              void* d_out, int out_size)
{
    const float* grid = (const float*)d_in[0];
    const int E = in_sizes[1] / 2;

    float* out    = (float*)d_out;
    float* nf     = out;                    // [NODES, C]
    float* ei_out = out + NF_ELEMS;         // [2, E] as float
    float* attr   = ei_out + 2 * (size_t)E; // [E, 2]

    fused_kernel<<<ATTR_BLOCKS + TRANS_BLOCKS, 256>>>(grid, nf, ei_out, attr, E);
}